// round 6
// baseline (speedup 1.0000x reference)
#include <cuda_runtime.h>
#include <cuda_bf16.h>
#include <cstdint>

// ShapeConv via warp-level mma.sync bf16 m16n8k16 implicit GEMM.
// Round-6: w_norm computed inside the main kernel during A staging
// (was a 29.6us uncoalesced tail kernel); finalize is now 9 loads/thread.

#define BB 32
#define CC 3
#define LL 8192
#define OO 128
#define KW 64
#define WW (LL - KW + 1)   /* 8129 valid windows */
#define NTILE 128
#define TPB 8              /* tiles per block */
#define NXB 8              /* gridDim.x ; NXB*TPB*NTILE >= WW */
#define KRED 192
#define APW 100            /* A pitch in 32-bit words (96 data + 4 pad) */

#define A_OFF    0u        /* 128*APW bf16x2 words = 51200 B */
#define XS32_OFF 51200u    /* 3*192 f32 */
#define SQ_OFF   53504u    /* 192 f32 */
#define S_OFF    54272u    /* 160 f32 half-window sums */
#define RED_OFF  54928u    /* 2*128 f32 (also reused as wsum during staging) */
#define XE_OFF   55952u    /* 3*96 bf16x2 */
#define XO_OFF   57104u    /* 3*96 bf16x2 */
#define SMEM_BYTES 58256

__device__ float g_part[BB * NXB * OO];   // partial maxima, plain stores
__device__ float g_wnorm[OO];             // 0.5*||w_o||^2, written by block (0,0)

__device__ __forceinline__ uint32_t pack_bf2(float lo, float hi) {
    __nv_bfloat162 h = __float22bfloat162_rn(make_float2(lo, hi));
    return *(uint32_t*)&h;
}
__device__ __forceinline__ void mma_bf16(float* d, const uint32_t* a,
                                         uint32_t b0, uint32_t b1) {
    asm volatile(
        "mma.sync.aligned.m16n8k16.row.col.f32.bf16.bf16.f32 "
        "{%0,%1,%2,%3}, {%4,%5,%6,%7}, {%8,%9}, {%0,%1,%2,%3};"
        : "+f"(d[0]), "+f"(d[1]), "+f"(d[2]), "+f"(d[3])
        : "r"(a[0]), "r"(a[1]), "r"(a[2]), "r"(a[3]), "r"(b0), "r"(b1));
}

extern "C" __global__ void __launch_bounds__(256, 2)
shapeconv_mma(const float* __restrict__ xg, const float* __restrict__ wg) {
    extern __shared__ char smem[];
    uint32_t* A_s  = (uint32_t*)(smem + A_OFF);     // [128][APW] bf16x2
    float*    xs32 = (float*)(smem + XS32_OFF);     // [3][192]
    float*    sq   = (float*)(smem + SQ_OFF);       // [192]
    float*    S_s  = (float*)(smem + S_OFF);        // [160]
    float*    red  = (float*)(smem + RED_OFF);      // [2][128]
    uint32_t* xe   = (uint32_t*)(smem + XE_OFF);    // [3][96]
    uint32_t* xo   = (uint32_t*)(smem + XO_OFF);    // [3][96]
    float*    wsum = red;                           // alias, staging phase only

    const int tid  = threadIdx.x;
    const int wid  = tid >> 5;
    const int lane = tid & 31;
    const int b    = blockIdx.y;
    const int xblk = blockIdx.x;

    const int m0  = (wid & 3) * 32;    // warp o-base
    const int n0w = (wid >> 2) * 64;   // warp t-base
    const int r4  = lane >> 2;
    const int q4  = lane & 3;

    if (tid < OO) wsum[tid] = 0.f;
    __syncthreads();

    // ---- A staging: weights -> packed bf16x2 [o][kpair]; fp32 norm piggyback ----
    for (int i = tid; i < OO * 96; i += 256) {
        int o = i / 96, kp = i % 96;
        const float* wp = wg + o * KRED + 2 * kp;
        float w0 = wp[0], w1 = wp[1];
        A_s[o * APW + kp] = pack_bf2(w0, w1);
        atomicAdd(&wsum[o], w0 * w0 + w1 * w1);
    }

    const float* xb = xg + b * CC * LL;
    float vrun = __int_as_float(0xff800000);

    // B-frag addressing: s = n0w + 8u + r4 + 2*q4 (+c*64); parity(s) = r4&1
    const uint32_t* xpar = (r4 & 1) ? xo : xe;
    const int wbase = (n0w + r4 + 2 * q4) >> 1;
    const int arow  = (m0 + r4) * APW + q4;

    // prefetch tile 0 x slice into regs (thread tid<192 owns position tid)
    float p0 = 0.f, p1 = 0.f, p2 = 0.f;
    {
        int g = xblk * TPB * NTILE + tid;
        if (tid < KRED && g < LL) { p0 = xb[g]; p1 = xb[LL + g]; p2 = xb[2 * LL + g]; }
    }
    __syncthreads();

    if (xblk == 0 && b == 0 && tid < OO) g_wnorm[tid] = 0.5f * wsum[tid];

    #pragma unroll 1
    for (int it = 0; it < TPB; ++it) {
        const int t0 = (xblk * TPB + it) * NTILE;

        // ---- phase A: spill prefetched regs to smem + squared sums ----
        if (tid < KRED) {
            xs32[tid] = p0; xs32[192 + tid] = p1; xs32[384 + tid] = p2;
            sq[tid] = p0 * p0 + p1 * p1 + p2 * p2;
        }
        __syncthreads();

        // ---- phase B: pack bf16 unfold sources + half-window sums ----
        for (int i = tid; i < CC * 96; i += 256) {
            int c = i / 96, j = i % 96;
            const float* xc = xs32 + c * 192;
            float v0 = xc[2 * j], v1 = xc[2 * j + 1];
            float v2 = (2 * j + 2 < 192) ? xc[2 * j + 2] : 0.f;
            xe[i] = pack_bf2(v0, v1);
            xo[i] = pack_bf2(v1, v2);
        }
        if (tid < 160) {
            float s = 0.f;
            #pragma unroll 8
            for (int k = 0; k < 32; ++k) s += sq[tid + k];
            S_s[tid] = s;
        }
        __syncthreads();

        // ---- prefetch next tile (latency hidden behind MMA) ----
        p0 = p1 = p2 = 0.f;
        if (it + 1 < TPB && tid < KRED) {
            int g = t0 + NTILE + tid;
            if (g < LL) { p0 = xb[g]; p1 = xb[LL + g]; p2 = xb[2 * LL + g]; }
        }

        // ---- MMA mainloop: 32 o x 64 t per warp, K=192 ----
        float acc[2][8][4];
        #pragma unroll
        for (int mi = 0; mi < 2; ++mi)
            #pragma unroll
            for (int nf = 0; nf < 8; ++nf)
                #pragma unroll
                for (int r = 0; r < 4; ++r) acc[mi][nf][r] = 0.f;

        #pragma unroll
        for (int c = 0; c < CC; ++c) {
            const uint32_t* xp = xpar + c * 96 + wbase;
            uint32_t bb[15];
            #pragma unroll
            for (int u = 0; u < 15; ++u) bb[u] = xp[4 * u];

            #pragma unroll
            for (int j = 0; j < 4; ++j) {
                const int coff = c * 32 + j * 8;
                uint32_t a[2][4];
                #pragma unroll
                for (int mi = 0; mi < 2; ++mi) {
                    const int base = arow + mi * 16 * APW + coff;
                    a[mi][0] = A_s[base];
                    a[mi][1] = A_s[base + 8 * APW];
                    a[mi][2] = A_s[base + 4];
                    a[mi][3] = A_s[base + 8 * APW + 4];
                }
                #pragma unroll
                for (int nf = 0; nf < 8; ++nf) {
                    uint32_t b0 = bb[2 * j + nf], b1 = bb[2 * j + nf + 1];
                    mma_bf16(acc[0][nf], a[0], b0, b1);
                    mma_bf16(acc[1][nf], a[1], b0, b1);
                }
            }
        }

        // ---- epilogue: feature = D - (S[n]+S[n+32]), masked, per-row max ----
        float mrow[4];
        #pragma unroll
        for (int r = 0; r < 4; ++r) mrow[r] = __int_as_float(0xff800000);
        #pragma unroll
        for (int mi = 0; mi < 2; ++mi)
            #pragma unroll
            for (int nf = 0; nf < 8; ++nf) {
                int ncol = n0w + nf * 8 + 2 * q4;
                float w0 = 0.5f * (S_s[ncol] + S_s[ncol + 32]);
                float w1 = 0.5f * (S_s[ncol + 1] + S_s[ncol + 33]);
                if (t0 + ncol >= WW)     w0 = __int_as_float(0x7f800000);
                if (t0 + ncol + 1 >= WW) w1 = __int_as_float(0x7f800000);
                float* d = acc[mi][nf];
                mrow[mi * 2]     = fmaxf(mrow[mi * 2],
                                         fmaxf(d[0] - w0, d[1] - w1));
                mrow[mi * 2 + 1] = fmaxf(mrow[mi * 2 + 1],
                                         fmaxf(d[2] - w0, d[3] - w1));
            }
        #pragma unroll
        for (int r = 0; r < 4; ++r) {
            mrow[r] = fmaxf(mrow[r], __shfl_xor_sync(0xffffffffu, mrow[r], 1));
            mrow[r] = fmaxf(mrow[r], __shfl_xor_sync(0xffffffffu, mrow[r], 2));
        }
        if (q4 == 0) {
            #pragma unroll
            for (int r = 0; r < 4; ++r) {
                int row = m0 + (r >> 1) * 16 + (r & 1) * 8 + r4;
                red[(wid >> 2) * 128 + row] = mrow[r];
            }
        }
        __syncthreads();
        if (tid < 128) vrun = fmaxf(vrun, fmaxf(red[tid], red[128 + tid]));
        // no extra sync: red is next written after two syncs (phases A/B)
    }

    if (tid < 128) g_part[(b * NXB + xblk) * OO + tid] = vrun;
}

// 9 coalesced loads per thread: 8 partials + 1 precomputed half-norm.
__global__ void shapeconv_finalize(float* __restrict__ out) {
    int idx = blockIdx.x * blockDim.x + threadIdx.x;
    if (idx >= BB * OO) return;
    int o = idx & (OO - 1);
    int b = idx >> 7;
    float v = __int_as_float(0xff800000);
    #pragma unroll
    for (int p = 0; p < NXB; ++p)
        v = fmaxf(v, g_part[(b * NXB + p) * OO + o]);
    out[idx] = -2.0f * (v - g_wnorm[o]);
}

extern "C" void kernel_launch(void* const* d_in, const int* in_sizes, int n_in,
                              void* d_out, int out_size) {
    const float* x = (const float*)d_in[0];
    const float* w = (const float*)d_in[1];
    float* out = (float*)d_out;

    cudaFuncSetAttribute(shapeconv_mma,
                         cudaFuncAttributeMaxDynamicSharedMemorySize, SMEM_BYTES);

    dim3 grid(NXB, BB);
    shapeconv_mma<<<grid, 256, SMEM_BYTES>>>(x, w);
    shapeconv_finalize<<<(BB * OO + 255) / 256, 256>>>(out);
}

// round 7
// speedup vs baseline: 2.2087x; 2.2087x over previous
#include <cuda_runtime.h>
#include <cuda_bf16.h>
#include <cstdint>

// ShapeConv via warp-level mma.sync bf16 m16n8k16 implicit GEMM.
// Round-7: w_norm piggybacked on A staging WITHOUT atomics (register
// accumulation + 1 shuffle; round-6's same-address shared atomics cost 80us).

#define BB 32
#define CC 3
#define LL 8192
#define OO 128
#define KW 64
#define WW (LL - KW + 1)   /* 8129 valid windows */
#define NTILE 128
#define TPB 8              /* tiles per block */
#define NXB 8              /* gridDim.x ; NXB*TPB*NTILE >= WW */
#define KRED 192
#define APW 100            /* A pitch in 32-bit words (96 data + 4 pad) */

#define A_OFF    0u        /* 128*APW bf16x2 words = 51200 B */
#define XS32_OFF 51200u    /* 3*192 f32 */
#define SQ_OFF   53504u    /* 192 f32 */
#define S_OFF    54272u    /* 160 f32 half-window sums */
#define RED_OFF  54928u    /* 2*128 f32 */
#define XE_OFF   55952u    /* 3*96 bf16x2 */
#define XO_OFF   57104u    /* 3*96 bf16x2 */
#define SMEM_BYTES 58256

__device__ float g_part[BB * NXB * OO];   // partial maxima, plain stores
__device__ float g_wnorm[OO];             // 0.5*||w_o||^2, written by block (0,0)

__device__ __forceinline__ uint32_t pack_bf2(float lo, float hi) {
    __nv_bfloat162 h = __float22bfloat162_rn(make_float2(lo, hi));
    return *(uint32_t*)&h;
}
__device__ __forceinline__ void mma_bf16(float* d, const uint32_t* a,
                                         uint32_t b0, uint32_t b1) {
    asm volatile(
        "mma.sync.aligned.m16n8k16.row.col.f32.bf16.bf16.f32 "
        "{%0,%1,%2,%3}, {%4,%5,%6,%7}, {%8,%9}, {%0,%1,%2,%3};"
        : "+f"(d[0]), "+f"(d[1]), "+f"(d[2]), "+f"(d[3])
        : "r"(a[0]), "r"(a[1]), "r"(a[2]), "r"(a[3]), "r"(b0), "r"(b1));
}

extern "C" __global__ void __launch_bounds__(256, 2)
shapeconv_mma(const float* __restrict__ xg, const float* __restrict__ wg) {
    extern __shared__ char smem[];
    uint32_t* A_s  = (uint32_t*)(smem + A_OFF);     // [128][APW] bf16x2
    float*    xs32 = (float*)(smem + XS32_OFF);     // [3][192]
    float*    sq   = (float*)(smem + SQ_OFF);       // [192]
    float*    S_s  = (float*)(smem + S_OFF);        // [160]
    float*    red  = (float*)(smem + RED_OFF);      // [2][128]
    uint32_t* xe   = (uint32_t*)(smem + XE_OFF);    // [3][96]
    uint32_t* xo   = (uint32_t*)(smem + XO_OFF);    // [3][96]

    const int tid  = threadIdx.x;
    const int wid  = tid >> 5;
    const int lane = tid & 31;
    const int b    = blockIdx.y;
    const int xblk = blockIdx.x;

    const int m0  = (wid & 3) * 32;    // warp o-base
    const int n0w = (wid >> 2) * 64;   // warp t-base
    const int r4  = lane >> 2;
    const int q4  = lane & 3;

    // ---- A staging: thread t owns o=t>>1, k-pairs [(t&1)*48, +48) ----
    // norm accumulated in a register; pair combined with one shuffle; NO atomics.
    {
        const int o_own  = tid >> 1;
        const int kbase  = (tid & 1) * 48;
        const float* wp  = wg + o_own * KRED + 2 * kbase;
        uint32_t* ap     = A_s + o_own * APW + kbase;
        float s = 0.f;
        #pragma unroll 8
        for (int j = 0; j < 48; ++j) {
            float w0 = wp[2 * j], w1 = wp[2 * j + 1];
            ap[j] = pack_bf2(w0, w1);
            s += w0 * w0 + w1 * w1;
        }
        s += __shfl_xor_sync(0xffffffffu, s, 1);
        if (b == 0 && xblk == 0 && (tid & 1) == 0) g_wnorm[o_own] = 0.5f * s;
    }

    const float* xb = xg + b * CC * LL;
    float vrun = __int_as_float(0xff800000);

    // B-frag addressing: s = n0w + 8u + r4 + 2*q4 (+c*64); parity(s) = r4&1
    const uint32_t* xpar = (r4 & 1) ? xo : xe;
    const int wbase = (n0w + r4 + 2 * q4) >> 1;
    const int arow  = (m0 + r4) * APW + q4;

    // prefetch tile 0 x slice into regs (thread tid<192 owns position tid)
    float p0 = 0.f, p1 = 0.f, p2 = 0.f;
    {
        int g = xblk * TPB * NTILE + tid;
        if (tid < KRED && g < LL) { p0 = xb[g]; p1 = xb[LL + g]; p2 = xb[2 * LL + g]; }
    }
    __syncthreads();

    #pragma unroll 1
    for (int it = 0; it < TPB; ++it) {
        const int t0 = (xblk * TPB + it) * NTILE;

        // ---- phase A: spill prefetched regs to smem + squared sums ----
        if (tid < KRED) {
            xs32[tid] = p0; xs32[192 + tid] = p1; xs32[384 + tid] = p2;
            sq[tid] = p0 * p0 + p1 * p1 + p2 * p2;
        }
        __syncthreads();

        // ---- phase B: pack bf16 unfold sources + half-window sums ----
        for (int i = tid; i < CC * 96; i += 256) {
            int c = i / 96, j = i % 96;
            const float* xc = xs32 + c * 192;
            float v0 = xc[2 * j], v1 = xc[2 * j + 1];
            float v2 = (2 * j + 2 < 192) ? xc[2 * j + 2] : 0.f;
            xe[i] = pack_bf2(v0, v1);
            xo[i] = pack_bf2(v1, v2);
        }
        if (tid < 160) {
            float s = 0.f;
            #pragma unroll 8
            for (int k = 0; k < 32; ++k) s += sq[tid + k];
            S_s[tid] = s;
        }
        __syncthreads();

        // ---- prefetch next tile (latency hidden behind MMA) ----
        p0 = p1 = p2 = 0.f;
        if (it + 1 < TPB && tid < KRED) {
            int g = t0 + NTILE + tid;
            if (g < LL) { p0 = xb[g]; p1 = xb[LL + g]; p2 = xb[2 * LL + g]; }
        }

        // ---- MMA mainloop: 32 o x 64 t per warp, K=192 ----
        float acc[2][8][4];
        #pragma unroll
        for (int mi = 0; mi < 2; ++mi)
            #pragma unroll
            for (int nf = 0; nf < 8; ++nf)
                #pragma unroll
                for (int r = 0; r < 4; ++r) acc[mi][nf][r] = 0.f;

        #pragma unroll
        for (int c = 0; c < CC; ++c) {
            const uint32_t* xp = xpar + c * 96 + wbase;
            uint32_t bb[15];
            #pragma unroll
            for (int u = 0; u < 15; ++u) bb[u] = xp[4 * u];

            #pragma unroll
            for (int j = 0; j < 4; ++j) {
                const int coff = c * 32 + j * 8;
                uint32_t a[2][4];
                #pragma unroll
                for (int mi = 0; mi < 2; ++mi) {
                    const int base = arow + mi * 16 * APW + coff;
                    a[mi][0] = A_s[base];
                    a[mi][1] = A_s[base + 8 * APW];
                    a[mi][2] = A_s[base + 4];
                    a[mi][3] = A_s[base + 8 * APW + 4];
                }
                #pragma unroll
                for (int nf = 0; nf < 8; ++nf) {
                    uint32_t b0 = bb[2 * j + nf], b1 = bb[2 * j + nf + 1];
                    mma_bf16(acc[0][nf], a[0], b0, b1);
                    mma_bf16(acc[1][nf], a[1], b0, b1);
                }
            }
        }

        // ---- epilogue: feature = D - (S[n]+S[n+32]), masked, per-row max ----
        float mrow[4];
        #pragma unroll
        for (int r = 0; r < 4; ++r) mrow[r] = __int_as_float(0xff800000);
        #pragma unroll
        for (int mi = 0; mi < 2; ++mi)
            #pragma unroll
            for (int nf = 0; nf < 8; ++nf) {
                int ncol = n0w + nf * 8 + 2 * q4;
                float w0 = 0.5f * (S_s[ncol] + S_s[ncol + 32]);
                float w1 = 0.5f * (S_s[ncol + 1] + S_s[ncol + 33]);
                if (t0 + ncol >= WW)     w0 = __int_as_float(0x7f800000);
                if (t0 + ncol + 1 >= WW) w1 = __int_as_float(0x7f800000);
                float* d = acc[mi][nf];
                mrow[mi * 2]     = fmaxf(mrow[mi * 2],
                                         fmaxf(d[0] - w0, d[1] - w1));
                mrow[mi * 2 + 1] = fmaxf(mrow[mi * 2 + 1],
                                         fmaxf(d[2] - w0, d[3] - w1));
            }
        #pragma unroll
        for (int r = 0; r < 4; ++r) {
            mrow[r] = fmaxf(mrow[r], __shfl_xor_sync(0xffffffffu, mrow[r], 1));
            mrow[r] = fmaxf(mrow[r], __shfl_xor_sync(0xffffffffu, mrow[r], 2));
        }
        if (q4 == 0) {
            #pragma unroll
            for (int r = 0; r < 4; ++r) {
                int row = m0 + (r >> 1) * 16 + (r & 1) * 8 + r4;
                red[(wid >> 2) * 128 + row] = mrow[r];
            }
        }
        __syncthreads();
        if (tid < 128) vrun = fmaxf(vrun, fmaxf(red[tid], red[128 + tid]));
        // no extra sync: red is next written after two syncs (phases A/B)
    }

    if (tid < 128) g_part[(b * NXB + xblk) * OO + tid] = vrun;
}

// 9 coalesced loads per thread: 8 partials + 1 precomputed half-norm.
__global__ void shapeconv_finalize(float* __restrict__ out) {
    int idx = blockIdx.x * blockDim.x + threadIdx.x;
    if (idx >= BB * OO) return;
    int o = idx & (OO - 1);
    int b = idx >> 7;
    float v = __int_as_float(0xff800000);
    #pragma unroll
    for (int p = 0; p < NXB; ++p)
        v = fmaxf(v, g_part[(b * NXB + p) * OO + o]);
    out[idx] = -2.0f * (v - g_wnorm[o]);
}

extern "C" void kernel_launch(void* const* d_in, const int* in_sizes, int n_in,
                              void* d_out, int out_size) {
    const float* x = (const float*)d_in[0];
    const float* w = (const float*)d_in[1];
    float* out = (float*)d_out;

    cudaFuncSetAttribute(shapeconv_mma,
                         cudaFuncAttributeMaxDynamicSharedMemorySize, SMEM_BYTES);

    dim3 grid(NXB, BB);
    shapeconv_mma<<<grid, 256, SMEM_BYTES>>>(x, w);
    shapeconv_finalize<<<(BB * OO + 255) / 256, 256>>>(out);
}

// round 8
// speedup vs baseline: 3.4397x; 1.5574x over previous
#include <cuda_runtime.h>
#include <cuda_bf16.h>
#include <cstdint>

// ShapeConv via warp-level mma.sync bf16 m16n8k16 implicit GEMM.
// Round-8: single fused kernel. Warp-cooperative coalesced A staging with free
// w_norm; flat balanced tile schedule (296 blocks = 2/SM x 7 tiles); last-block
// ticket does the final reduction inline (no finalize kernel, no init kernel).

#define BB 32
#define CC 3
#define LL 8192
#define OO 128
#define KW 64
#define WW (LL - KW + 1)   /* 8129 valid windows */
#define NTILE 128
#define KRED 192
#define APW 100            /* A pitch in 32-bit words (96 data + 4 pad) */
#define NBLK 296           /* 2 CTAs per SM, one wave */
#define NTPB 7             /* tile slots per block; 296*7 >= 2048 */
#define TILES_TOTAL (BB * 64)   /* 2048 */

#define A_OFF    0u        /* 128*APW bf16x2 words = 51200 B */
#define XS32_OFF 51200u    /* 3*192 f32 */
#define SQ_OFF   53504u    /* 192 f32 */
#define S_OFF    54272u    /* 160 f32 half-window sums */
#define RED_OFF  54928u    /* 2*128 f32 */
#define XE_OFF   55952u    /* 3*96 bf16x2 */
#define XO_OFF   57104u    /* 3*96 bf16x2 */
#define WS_OFF   58256u    /* 128 f32: 0.5*||w_o||^2 */
#define SMEM_BYTES 58768

__device__ unsigned int g_max[BB * OO];   // monotone-mapped maxima (zero-init)
__device__ unsigned int g_counter;        // ticket (zero-init)

__device__ __forceinline__ unsigned int f2mono(float f) {
    unsigned int u = __float_as_uint(f);
    return (u & 0x80000000u) ? ~u : (u | 0x80000000u);
}
__device__ __forceinline__ float mono2f(unsigned int m) {
    unsigned int u = (m & 0x80000000u) ? (m & 0x7fffffffu) : ~m;
    return __uint_as_float(u);
}
__device__ __forceinline__ uint32_t pack_bf2(float lo, float hi) {
    __nv_bfloat162 h = __float22bfloat162_rn(make_float2(lo, hi));
    return *(uint32_t*)&h;
}
__device__ __forceinline__ void mma_bf16(float* d, const uint32_t* a,
                                         uint32_t b0, uint32_t b1) {
    asm volatile(
        "mma.sync.aligned.m16n8k16.row.col.f32.bf16.bf16.f32 "
        "{%0,%1,%2,%3}, {%4,%5,%6,%7}, {%8,%9}, {%0,%1,%2,%3};"
        : "+f"(d[0]), "+f"(d[1]), "+f"(d[2]), "+f"(d[3])
        : "r"(a[0]), "r"(a[1]), "r"(a[2]), "r"(a[3]), "r"(b0), "r"(b1));
}

extern "C" __global__ void __launch_bounds__(256, 2)
shapeconv_fused(const float* __restrict__ xg, const float* __restrict__ wg,
                float* __restrict__ out) {
    extern __shared__ char smem[];
    uint32_t* A_s  = (uint32_t*)(smem + A_OFF);     // [128][APW] bf16x2
    float*    xs32 = (float*)(smem + XS32_OFF);     // [3][192]
    float*    sq   = (float*)(smem + SQ_OFF);       // [192]
    float*    S_s  = (float*)(smem + S_OFF);        // [160]
    float*    red  = (float*)(smem + RED_OFF);      // [2][128]
    uint32_t* xe   = (uint32_t*)(smem + XE_OFF);    // [3][96]
    uint32_t* xo   = (uint32_t*)(smem + XO_OFF);    // [3][96]
    float*    ws   = (float*)(smem + WS_OFF);       // [128]

    const int tid  = threadIdx.x;
    const int wid  = tid >> 5;
    const int lane = tid & 31;
    const int blk  = blockIdx.x;

    const int m0  = (wid & 3) * 32;    // warp o-base
    const int n0w = (wid >> 2) * 64;   // warp t-base
    const int r4  = lane >> 2;
    const int q4  = lane & 3;

    // ---- A staging: warp w owns o-rows [16w,16w+16); coalesced float2 loads,
    // conflict-free STS, shuffle-reduced squared norm -> ws[o]. No atomics. ----
    {
        const int o0w = wid * 16;
        #pragma unroll 4
        for (int oi = 0; oi < 16; ++oi) {
            const int o = o0w + oi;
            const float2* wp = (const float2*)(wg + o * KRED);
            float2 v0 = wp[lane], v1 = wp[lane + 32], v2 = wp[lane + 64];
            uint32_t* ap = A_s + o * APW;
            ap[lane]      = pack_bf2(v0.x, v0.y);
            ap[lane + 32] = pack_bf2(v1.x, v1.y);
            ap[lane + 64] = pack_bf2(v2.x, v2.y);
            float s = v0.x * v0.x + v0.y * v0.y + v1.x * v1.x + v1.y * v1.y
                    + v2.x * v2.x + v2.y * v2.y;
            #pragma unroll
            for (int d = 16; d; d >>= 1)
                s += __shfl_xor_sync(0xffffffffu, s, d);
            if (lane == 0) ws[o] = 0.5f * s;
        }
    }

    // B-frag addressing: s = n0w + 8u + r4 + 2*q4 (+c*64); parity(s) = r4&1
    const uint32_t* xpar = (r4 & 1) ? xo : xe;
    const int wbase = (n0w + r4 + 2 * q4) >> 1;
    const int arow  = (m0 + r4) * APW + q4;

    // ---- flat tile schedule: tile tl -> (b = tl>>6, t0 = (tl&63)*128) ----
    int tl = blk * NTPB;

    // prefetch first tile's x slice (thread tid<192 owns position tid)
    float p0 = 0.f, p1 = 0.f, p2 = 0.f;
    if (tl < TILES_TOTAL && tid < KRED) {
        const float* xp = xg + (tl >> 6) * CC * LL;
        int g = ((tl & 63) << 7) + tid;
        if (g < LL) { p0 = xp[g]; p1 = xp[LL + g]; p2 = xp[2 * LL + g]; }
    }
    __syncthreads();

    int   cur_b = -1;
    float vrun  = __int_as_float(0xff800000);

    #pragma unroll 1
    for (int i = 0; i < NTPB; ++i, ++tl) {
        if (tl >= TILES_TOTAL) break;
        const int tb = tl >> 6;
        const int t0 = (tl & 63) << 7;

        if (tb != cur_b) {                      // batch boundary: flush partial max
            if (cur_b >= 0 && tid < 128)
                atomicMax(&g_max[cur_b * OO + tid], f2mono(vrun));
            vrun = __int_as_float(0xff800000);
            cur_b = tb;
        }

        // ---- phase A: spill prefetched regs to smem + squared sums ----
        if (tid < KRED) {
            xs32[tid] = p0; xs32[192 + tid] = p1; xs32[384 + tid] = p2;
            sq[tid] = p0 * p0 + p1 * p1 + p2 * p2;
        }
        __syncthreads();

        // ---- phase B: pack bf16 unfold sources + half-window sums ----
        for (int u = tid; u < CC * 96; u += 256) {
            int c = u / 96, j = u % 96;
            const float* xc = xs32 + c * 192;
            float v0 = xc[2 * j], v1 = xc[2 * j + 1];
            float v2 = (2 * j + 2 < 192) ? xc[2 * j + 2] : 0.f;
            xe[u] = pack_bf2(v0, v1);
            xo[u] = pack_bf2(v1, v2);
        }
        if (tid < 160) {
            float s = 0.f;
            #pragma unroll 8
            for (int k = 0; k < 32; ++k) s += sq[tid + k];
            S_s[tid] = s;
        }
        __syncthreads();

        // ---- prefetch next tile (latency hidden behind MMA) ----
        p0 = p1 = p2 = 0.f;
        if (i + 1 < NTPB && tl + 1 < TILES_TOTAL && tid < KRED) {
            const float* xp = xg + ((tl + 1) >> 6) * CC * LL;
            int g = (((tl + 1) & 63) << 7) + tid;
            if (g < LL) { p0 = xp[g]; p1 = xp[LL + g]; p2 = xp[2 * LL + g]; }
        }

        // ---- MMA mainloop: 32 o x 64 t per warp, K=192 ----
        float acc[2][8][4];
        #pragma unroll
        for (int mi = 0; mi < 2; ++mi)
            #pragma unroll
            for (int nf = 0; nf < 8; ++nf)
                #pragma unroll
                for (int r = 0; r < 4; ++r) acc[mi][nf][r] = 0.f;

        #pragma unroll
        for (int c = 0; c < CC; ++c) {
            const uint32_t* xp = xpar + c * 96 + wbase;
            uint32_t bb[15];
            #pragma unroll
            for (int u = 0; u < 15; ++u) bb[u] = xp[4 * u];

            #pragma unroll
            for (int j = 0; j < 4; ++j) {
                const int coff = c * 32 + j * 8;
                uint32_t a[2][4];
                #pragma unroll
                for (int mi = 0; mi < 2; ++mi) {
                    const int base = arow + mi * 16 * APW + coff;
                    a[mi][0] = A_s[base];
                    a[mi][1] = A_s[base + 8 * APW];
                    a[mi][2] = A_s[base + 4];
                    a[mi][3] = A_s[base + 8 * APW + 4];
                }
                #pragma unroll
                for (int nf = 0; nf < 8; ++nf) {
                    uint32_t b0 = bb[2 * j + nf], b1 = bb[2 * j + nf + 1];
                    mma_bf16(acc[0][nf], a[0], b0, b1);
                    mma_bf16(acc[1][nf], a[1], b0, b1);
                }
            }
        }

        // ---- epilogue: feature = D - (S[n]+S[n+32]), masked, per-row max ----
        float mrow[4];
        #pragma unroll
        for (int r = 0; r < 4; ++r) mrow[r] = __int_as_float(0xff800000);
        #pragma unroll
        for (int mi = 0; mi < 2; ++mi)
            #pragma unroll
            for (int nf = 0; nf < 8; ++nf) {
                int ncol = n0w + nf * 8 + 2 * q4;
                float w0 = 0.5f * (S_s[ncol] + S_s[ncol + 32]);
                float w1 = 0.5f * (S_s[ncol + 1] + S_s[ncol + 33]);
                if (t0 + ncol >= WW)     w0 = __int_as_float(0x7f800000);
                if (t0 + ncol + 1 >= WW) w1 = __int_as_float(0x7f800000);
                float* d = acc[mi][nf];
                mrow[mi * 2]     = fmaxf(mrow[mi * 2],
                                         fmaxf(d[0] - w0, d[1] - w1));
                mrow[mi * 2 + 1] = fmaxf(mrow[mi * 2 + 1],
                                         fmaxf(d[2] - w0, d[3] - w1));
            }
        #pragma unroll
        for (int r = 0; r < 4; ++r) {
            mrow[r] = fmaxf(mrow[r], __shfl_xor_sync(0xffffffffu, mrow[r], 1));
            mrow[r] = fmaxf(mrow[r], __shfl_xor_sync(0xffffffffu, mrow[r], 2));
        }
        if (q4 == 0) {
            #pragma unroll
            for (int r = 0; r < 4; ++r) {
                int row = m0 + (r >> 1) * 16 + (r & 1) * 8 + r4;
                red[(wid >> 2) * 128 + row] = mrow[r];
            }
        }
        __syncthreads();
        if (tid < 128) vrun = fmaxf(vrun, fmaxf(red[tid], red[128 + tid]));
        // no extra sync needed: red is rewritten only after two later syncs
    }

    if (cur_b >= 0 && tid < 128)
        atomicMax(&g_max[cur_b * OO + tid], f2mono(vrun));

    // ---- last-block inline finalize ----
    __threadfence();
    __shared__ unsigned int s_last;
    if (tid == 0)
        s_last = (atomicAdd(&g_counter, 1u) == NBLK - 1u) ? 1u : 0u;
    __syncthreads();
    if (s_last) {
        for (int idx = tid; idx < BB * OO; idx += 256) {
            int o = idx & (OO - 1);
            float v = mono2f(g_max[idx]);
            out[idx] = -2.0f * (v - ws[o]);
            g_max[idx] = 0u;               // reset for next graph replay
        }
        if (tid == 0) g_counter = 0u;
    }
}

extern "C" void kernel_launch(void* const* d_in, const int* in_sizes, int n_in,
                              void* d_out, int out_size) {
    const float* x = (const float*)d_in[0];
    const float* w = (const float*)d_in[1];
    float* out = (float*)d_out;

    cudaFuncSetAttribute(shapeconv_fused,
                         cudaFuncAttributeMaxDynamicSharedMemorySize, SMEM_BYTES);
    shapeconv_fused<<<NBLK, 256, SMEM_BYTES>>>(x, w, out);
}